// round 16
// baseline (speedup 1.0000x reference)
#include <cuda_runtime.h>
#include <cuda_bf16.h>
#include <cstdint>

#define M_ROWS 4096
#define N_HID  16384
#define K_DIM  768
#define K_SPARSE 32
#define MAX_CAND 56
#define RANK_SEL 36
#define CAP      1024
#define THRESH   2.0f

// GEMM tiling: 128x64 CTA tile, 8 warps of 32x32, BK=32 bf16, paired 4-stage pipeline
#define BKW 16                   // words (4B) per smem row
#define TS  20                   // padded word stride (conflict-free for ldmatrix)
#define NKTILE (K_DIM / 32)      // 24
#define NPAIR  (NKTILE / 2)      // 12
#define STG_A (128 * TS)         // A stage words
#define STG_B (64 * TS)          // B stage words
#define STAGE_TOT (STG_A + STG_B)
#define NSTAGE 4

// ---------------- device scratch ----------------
__device__ __nv_bfloat16 X16[M_ROWS * K_DIM];
__device__ __nv_bfloat16 W16[N_HID * K_DIM];
__device__ int   g_ccnt[M_ROWS];
__device__ int   g_cidx[(size_t)M_ROWS * CAP];
__device__ float g_cval[(size_t)M_ROWS * CAP];
__device__ float g_invnorm[N_HID];

// ---------------- PTX helpers ----------------
__device__ __forceinline__ uint32_t cvta_shared(const void* p) {
    return (uint32_t)__cvta_generic_to_shared(p);
}
#define CP_ASYNC16(dst, src) \
    asm volatile("cp.async.cg.shared.global [%0], [%1], 16;\n" :: "r"(dst), "l"(src))
#define CP_COMMIT() asm volatile("cp.async.commit_group;\n" ::: "memory")
#define CP_WAIT0()  asm volatile("cp.async.wait_group 0;\n" ::: "memory")

#define LDSM_X4(r, addr) \
    asm volatile("ldmatrix.sync.aligned.m8n8.x4.shared.b16 {%0,%1,%2,%3}, [%4];" \
        : "=r"((r)[0]), "=r"((r)[1]), "=r"((r)[2]), "=r"((r)[3]) : "r"(addr))

__device__ __forceinline__ void mma_bf16(float* d, const uint32_t* a, const uint32_t* b)
{
    asm volatile(
        "mma.sync.aligned.m16n8k16.row.col.f32.bf16.bf16.f32 "
        "{%0,%1,%2,%3}, {%4,%5,%6,%7}, {%8,%9}, {%0,%1,%2,%3};\n"
        : "+f"(d[0]), "+f"(d[1]), "+f"(d[2]), "+f"(d[3])
        : "r"(a[0]), "r"(a[1]), "r"(a[2]), "r"(a[3]), "r"(b[0]), "r"(b[1]));
}

// ---------------- fused conversion kernel (float4 vectorized) ----------------
// blocks [0, XB4): convert X (4 elems/thread); blocks [XB4, XB4+WB): W rows + norms
#define XB4 ((M_ROWS * K_DIM) / 1024)   // 3072
#define WB  (N_HID / 8)                 // 2048

__global__ void convert_all_kernel(const float* __restrict__ X,
                                   const float* __restrict__ W)
{
    if (blockIdx.x < XB4) {
        const int i = blockIdx.x * 256 + threadIdx.x;     // float4 index
        const float4 v = ((const float4*)X)[i];
        __nv_bfloat162 lo = __floats2bfloat162_rn(v.x, v.y);
        __nv_bfloat162 hi = __floats2bfloat162_rn(v.z, v.w);
        uint2 pk;
        pk.x = *(const uint32_t*)&lo;
        pk.y = *(const uint32_t*)&hi;
        *(uint2*)(X16 + 4 * (size_t)i) = pk;
        if (i < M_ROWS) g_ccnt[i] = 0;
    } else {
        const int row  = (blockIdx.x - XB4) * 8 + (threadIdx.x >> 5);
        const int lane = threadIdx.x & 31;
        const float4* w4 = (const float4*)(W + (size_t)row * K_DIM);
        float s = 0.0f;
#pragma unroll
        for (int k = 0; k < K_DIM / 128; k++) {           // 6 iters
            const float4 v = w4[lane + 32 * k];
            s = fmaf(v.x, v.x, s); s = fmaf(v.y, v.y, s);
            s = fmaf(v.z, v.z, s); s = fmaf(v.w, v.w, s);
            __nv_bfloat162 lo = __floats2bfloat162_rn(v.x, v.y);
            __nv_bfloat162 hi = __floats2bfloat162_rn(v.z, v.w);
            uint2 pk;
            pk.x = *(const uint32_t*)&lo;
            pk.y = *(const uint32_t*)&hi;
            *(uint2*)(W16 + (size_t)row * K_DIM + 4 * (lane + 32 * k)) = pk;
        }
#pragma unroll
        for (int o = 16; o; o >>= 1) s += __shfl_xor_sync(0xFFFFFFFFu, s, o);
        if (lane == 0) g_invnorm[row] = rsqrtf(s);
    }
}

// ---------------- encoder GEMM (bf16 mma.sync + ldmatrix, paired stages) -------
__device__ __forceinline__ void ldtile16(int m0, int n0, int kt,
                                         uint32_t* As, uint32_t* Bs, int t)
{
#pragma unroll
    for (int it = 0; it < 2; it++) {         // A: 128 rows x 4 granules
        const int g = t + it * 256;
        const int r = g >> 2;
        const int c = g & 3;
        CP_ASYNC16(cvta_shared(As + r * TS + c * 4),
                   X16 + (size_t)(m0 + r) * K_DIM + kt + c * 8);
    }
    {                                        // B: 64 rows x 4 granules
        const int r = t >> 2;
        const int c = t & 3;
        CP_ASYNC16(cvta_shared(Bs + r * TS + c * 4),
                   W16 + (size_t)(n0 + r) * K_DIM + kt + c * 8);
    }
}

__device__ __forceinline__ void cand_append(int row, int col, float v)
{
    if (v > THRESH) {
        const int q = atomicAdd(&g_ccnt[row], 1);
        if (q < CAP) {
            g_cidx[(size_t)row * CAP + q] = col;
            g_cval[(size_t)row * CAP + q] = v;
        }
    }
}

__global__ void __launch_bounds__(256, 3) encode_gemm(
    const float* __restrict__ bias, float* __restrict__ enc)
{
    extern __shared__ uint32_t smem[];   // NSTAGE * STAGE_TOT words

    const int t    = threadIdx.x;
    const int lane = t & 31;
    const int wid  = t >> 5;
    const int m0   = blockIdx.x * 128;
    const int n0   = blockIdx.y * 64;
    const int wm   = (wid & 3) * 32;     // warp m offset (4 warps in M)
    const int wn   = (wid >> 2) * 32;    // warp n offset (2 warps in N)
    const int fg   = lane >> 2;
    const int fc   = lane & 3;

    // per-thread ldmatrix address offsets (bytes) within a stage
    const uint32_t aoff = ((wm + (lane & 15)) * TS + ((lane >> 4) << 2)) * 4;
    const uint32_t boff = ((wn + (lane & 7) + ((lane >> 4) << 3)) * TS
                           + (((lane >> 3) & 1) << 2)) * 4;

    float acc[2][4][4];
#pragma unroll
    for (int i = 0; i < 2; i++)
#pragma unroll
        for (int j = 0; j < 4; j++)
#pragma unroll
            for (int r = 0; r < 4; r++) acc[i][j][r] = 0.0f;

    // prologue: pair 0 (k-tiles 0,1) -> stages 0,1
    ldtile16(m0, n0, 0,  smem,             smem + STG_A,             t);
    ldtile16(m0, n0, 32, smem + STAGE_TOT, smem + STAGE_TOT + STG_A, t);
    CP_COMMIT();

    // zero this CTA's 128x64 output tile (overlapped; DRAM is idle in this kernel)
    {
        const float4 z = make_float4(0.f, 0.f, 0.f, 0.f);
#pragma unroll
        for (int k2 = 0; k2 < 8; k2++) {
            const int j = t + k2 * 256;          // 0..2047 float4 slots
            const int r = j >> 4;                // row 0..127
            const int c4 = j & 15;               // float4 col 0..15
            *(float4*)(enc + (size_t)(m0 + r) * N_HID + n0 + c4 * 4) = z;
        }
    }

    for (int p = 0; p < NPAIR; p++) {
        CP_WAIT0();                // pair p's loads complete (issued last iter / prologue)
        __syncthreads();           // all warps done reading pair p-1's stages

        if (p + 1 < NPAIR) {       // prefetch pair p+1 into the slot freed by pair p-1
            uint32_t* s0 = smem + (((p + 1) & 1) * 2) * STAGE_TOT;
            ldtile16(m0, n0, (2 * (p + 1)) * 32,     s0,             s0 + STG_A,             t);
            ldtile16(m0, n0, (2 * (p + 1) + 1) * 32, s0 + STAGE_TOT, s0 + STAGE_TOT + STG_A, t);
        }
        CP_COMMIT();

        // compute k-tiles 2p, 2p+1 from stages (p&1)*2, (p&1)*2+1
#pragma unroll
        for (int half = 0; half < 2; half++) {
            const uint32_t Ab = cvta_shared(smem + ((p & 1) * 2 + half) * STAGE_TOT);
            const uint32_t Bb = Ab + STG_A * 4;
#pragma unroll
            for (int ks = 0; ks < BKW; ks += 8) {
                uint32_t a[2][4], b[2][4];
#pragma unroll
                for (int mi = 0; mi < 2; mi++)
                    LDSM_X4(a[mi], Ab + aoff + (mi * 16 * TS + ks) * 4);
#pragma unroll
                for (int njp = 0; njp < 2; njp++)
                    LDSM_X4(b[njp], Bb + boff + (njp * 16 * TS + ks) * 4);
#pragma unroll
                for (int mi = 0; mi < 2; mi++)
#pragma unroll
                    for (int nj = 0; nj < 4; nj++)
                        mma_bf16(acc[mi][nj], a[mi], &b[nj >> 1][(nj & 1) * 2]);
            }
        }
    }

    // epilogue: threshold + append candidates (no dense store)
#pragma unroll
    for (int nj = 0; nj < 4; nj++) {
        const int col = n0 + wn + nj * 8 + fc * 2;
        const float b0 = bias[col], b1 = bias[col + 1];
#pragma unroll
        for (int mi = 0; mi < 2; mi++) {
            const int row = m0 + wm + mi * 16 + fg;
            cand_append(row,     col,     acc[mi][nj][0] + b0);
            cand_append(row,     col + 1, acc[mi][nj][1] + b1);
            cand_append(row + 8, col,     acc[mi][nj][2] + b0);
            cand_append(row + 8, col + 1, acc[mi][nj][3] + b1);
        }
    }
}

// ---------------- fused top-k fixup + decode ----------------
__device__ __forceinline__ unsigned int f2u(float f)
{
    unsigned int b = __float_as_uint(f);
    return (b & 0x80000000u) ? ~b : (b | 0x80000000u);
}

// exact key of k-th largest over arr[0..n) (FALLBACK path only)
__device__ unsigned int radix_key(const float* arr, int n, int k,
                                  unsigned int* hist, unsigned int* cbuf,
                                  unsigned int* prefixSh, unsigned int* kSh, int t)
{
    if (t == 0) { *prefixSh = 0; *kSh = (unsigned int)k; }
    __syncthreads();
    for (int pass = 3; pass >= 0; --pass) {
        const int shift = pass * 8;
        hist[t] = 0;
        __syncthreads();
        const unsigned int prefix = *prefixSh;
        for (int i = t; i < n; i += 256) {
            const unsigned int u = f2u(arr[i]);
            bool cand = (pass == 3) || ((u >> (shift + 8)) == (prefix >> (shift + 8)));
            if (cand) atomicAdd(&hist[(u >> shift) & 0xFFu], 1u);
        }
        __syncthreads();
        cbuf[t] = hist[t];
        __syncthreads();
        for (int off = 1; off < 256; off <<= 1) {
            unsigned int v   = cbuf[t];
            unsigned int add = (t + off < 256) ? cbuf[t + off] : 0u;
            __syncthreads();
            cbuf[t] = v + add;
            __syncthreads();
        }
        const unsigned int kcur  = *kSh;
        const unsigned int here  = cbuf[t];
        const unsigned int above = (t < 255) ? cbuf[t + 1] : 0u;
        __syncthreads();
        if (here >= kcur && above < kcur) {
            *prefixSh = prefix | ((unsigned int)t << shift);
            *kSh = kcur - above;
        }
        __syncthreads();
    }
    return *prefixSh;
}

__global__ void __launch_bounds__(256) fixup_decode_kernel(
    const float* __restrict__ X, const float* __restrict__ W,
    const float* __restrict__ bias, float* __restrict__ enc,
    float* __restrict__ dec)
{
    const int row = blockIdx.x;
    float* p = enc + (size_t)row * N_HID;
    const int t = threadIdx.x;

    __shared__ __align__(16) float xrow[K_DIM];
    __shared__ float cval_s[CAP];          // staged candidate values
    __shared__ int   cidx_s[CAP];          // staged candidate indices
    __shared__ int   histo[1024];          // single-pass bucket histogram
    __shared__ int   tsum[256];            // per-thread bucket sums / scan
    __shared__ int   bstar;
    __shared__ unsigned int prefixSh, kSh; // fallback radix state
    __shared__ int nsel2, nacc;
    __shared__ int   sel_i[MAX_CAND];
    __shared__ float sel_v[MAX_CAND];
    __shared__ int   jsel[MAX_CAND];
    __shared__ float coef[MAX_CAND];

    if (t < K_DIM / 4)
        ((float4*)xrow)[t] = ((const float4*)(X + (size_t)row * K_DIM))[t];
    if (t == 0) { nsel2 = 0; nacc = 0; }
    histo[t] = 0; histo[t + 256] = 0; histo[t + 512] = 0; histo[t + 768] = 0;
    __syncthreads();

    const int cnt = g_ccnt[row];
    if (cnt >= RANK_SEL && cnt <= CAP) {
        // ---- single-pass histogram select; stage candidates in smem ----
        for (int i = t; i < cnt; i += 256) {
            const float v = g_cval[(size_t)row * CAP + i];
            cval_s[i] = v;
            cidx_s[i] = g_cidx[(size_t)row * CAP + i];
            int b = (int)((f2u(v) >> 16) - 0xC000u);
            b = (b > 1023) ? 1023 : b;
            atomicAdd(&histo[b], 1);
        }
        __syncthreads();
        tsum[t] = histo[4 * t] + histo[4 * t + 1] + histo[4 * t + 2] + histo[4 * t + 3];
        __syncthreads();
        for (int off = 1; off < 256; off <<= 1) {       // suffix scan of tsum
            int v = tsum[t];
            int add = (t + off < 256) ? tsum[t + off] : 0;
            __syncthreads();
            tsum[t] = v + add;
            __syncthreads();
        }
        {
            const int above = (t < 255) ? tsum[t + 1] : 0;
            int suf = above;
#pragma unroll
            for (int k2 = 3; k2 >= 0; k2--) {           // suffix within this thread's 4 bins
                const int b = 4 * t + k2;
                suf += histo[b];
                if (suf >= RANK_SEL && (suf - histo[b]) < RANK_SEL) bstar = b;
            }
        }
        __syncthreads();
        const int bth = bstar;
        for (int i = t; i < cnt; i += 256) {
            int b = (int)((f2u(cval_s[i]) >> 16) - 0xC000u);
            b = (b > 1023) ? 1023 : b;
            if (b >= bth) {
                const int q = atomicAdd(&nsel2, 1);
                if (q < MAX_CAND) sel_i[q] = cidx_s[i];
            }
        }
    } else {
        // fallback (statistically never taken): exact full-row recompute
        for (int n = t; n < N_HID; n += 256) {
            const float* wr = W + (size_t)n * K_DIM;
            float s = 0.0f;
            for (int k2 = 0; k2 < K_DIM; k2++) s = fmaf(xrow[k2], wr[k2], s);
            p[n] = s + bias[n];
        }
        __syncthreads();
        const unsigned int key = radix_key(p, N_HID, RANK_SEL,
                                           (unsigned int*)histo, (unsigned int*)tsum,
                                           &prefixSh, &kSh, t);
        for (int i = t; i < N_HID; i += 256) {
            if (f2u(p[i]) >= key) {
                const int q = atomicAdd(&nsel2, 1);
                if (q < MAX_CAND) sel_i[q] = i;
            }
        }
        __syncthreads();
        float4 z4 = make_float4(0.f, 0.f, 0.f, 0.f);
        for (int i = t; i < N_HID / 4; i += 256) ((float4*)p)[i] = z4;  // re-zero
    }
    __syncthreads();
    const int nc = (nsel2 < MAX_CAND) ? nsel2 : MAX_CAND;

    // exact fp32 dot products for selected candidates (one warp per candidate,
    // float4 loads: 6 LDG.128 + 6 LDS.128 per lane)
    const int lane = t & 31, w = t >> 5;
    const float4* xr4 = (const float4*)xrow;
    for (int i = w; i < nc; i += 8) {
        const float4* wr4 = (const float4*)(W + (size_t)sel_i[i] * K_DIM);
        float s = 0.0f;
#pragma unroll
        for (int k2 = 0; k2 < K_DIM / 128; k2++) {       // 6 iters
            const float4 wv = wr4[lane + 32 * k2];
            const float4 xv = xr4[lane + 32 * k2];
            s = fmaf(xv.x, wv.x, s);
            s = fmaf(xv.y, wv.y, s);
            s = fmaf(xv.z, wv.z, s);
            s = fmaf(xv.w, wv.w, s);
        }
#pragma unroll
        for (int o = 16; o; o >>= 1) s += __shfl_xor_sync(0xFFFFFFFFu, s, o);
        if (lane == 0) sel_v[i] = s + bias[sel_i[i]];
    }
    __syncthreads();

    // exact rank; keep if fewer than K_SPARSE strictly greater (keeps ties);
    // scatter exact value to enc and gather (idx, coef) for the fused decode
    if (t < nc) {
        const float v = sel_v[t];
        int cg = 0;
        for (int j = 0; j < nc; j++) cg += (sel_v[j] > v);
        if (cg < K_SPARSE) {
            const int idx = sel_i[t];
            p[idx] = v;
            const int q = atomicAdd(&nacc, 1);
            jsel[q] = idx;
            coef[q] = v * g_invnorm[idx];
        }
    }
    __syncthreads();

    // fused decode: dec[row,:] = sum_j coef_j * W[jsel_j,:]  (W rows are L1-hot)
    const int ns = nacc;
    float a0 = 0.0f, a1 = 0.0f, a2 = 0.0f;
    for (int j = 0; j < ns; ++j) {
        const float* wr = W + (size_t)jsel[j] * K_DIM;
        const float cf = coef[j];
        a0 = fmaf(cf, wr[t],       a0);
        a1 = fmaf(cf, wr[t + 256], a1);
        a2 = fmaf(cf, wr[t + 512], a2);
    }
    float* o = dec + (size_t)row * K_DIM;
    o[t] = a0; o[t + 256] = a1; o[t + 512] = a2;
}

// ---------------- launch ----------------
extern "C" void kernel_launch(void* const* d_in, const int* in_sizes, int n_in,
                              void* d_out, int out_size)
{
    const float* x = (const float*)d_in[0];
    const float* W = (const float*)d_in[1];
    const float* b = (const float*)d_in[2];
    float* out = (float*)d_out;

    float* dec = out;                               // [4096, 768]
    float* enc = out + (size_t)M_ROWS * K_DIM;      // [4096, 16384]

    convert_all_kernel<<<XB4 + WB, 256>>>(x, W);

    const int dyn_smem = NSTAGE * STAGE_TOT * 4;    // 61440 bytes
    cudaFuncSetAttribute(encode_gemm, cudaFuncAttributeMaxDynamicSharedMemorySize, dyn_smem);

    dim3 ggrid(M_ROWS / 128, N_HID / 64);           // x fast: consecutive CTAs share B tile
    encode_gemm<<<ggrid, 256, dyn_smem>>>(b, enc);
    fixup_decode_kernel<<<M_ROWS, 256>>>(x, W, b, enc, dec);
}

// round 17
// speedup vs baseline: 1.1498x; 1.1498x over previous
#include <cuda_runtime.h>
#include <cuda_bf16.h>
#include <cstdint>

#define M_ROWS 4096
#define N_HID  16384
#define K_DIM  768
#define K_SPARSE 32
#define MAX_CAND 56
#define RANK_SEL 36
#define CAP      1024
#define THRESH   2.0f

// GEMM tiling: 128x64 CTA tile, 8 warps of 32x32, BK=32 bf16, 3-stage pipeline
#define BKW 16                   // words (4B) per smem row
#define TS  20                   // padded word stride (conflict-free for ldmatrix)
#define NKTILE (K_DIM / 32)      // 24
#define STG_A (128 * TS)         // A stage words
#define STG_B (64 * TS)          // B stage words
#define STAGE_TOT (STG_A + STG_B)
#define NSTAGE 3

// ---------------- device scratch ----------------
__device__ __nv_bfloat16 X16[M_ROWS * K_DIM];
__device__ __nv_bfloat16 W16[N_HID * K_DIM];
__device__ int   g_ccnt[M_ROWS];
__device__ int   g_cidx[(size_t)M_ROWS * CAP];
__device__ float g_cval[(size_t)M_ROWS * CAP];
__device__ float g_invnorm[N_HID];

// ---------------- PTX helpers ----------------
__device__ __forceinline__ uint32_t cvta_shared(const void* p) {
    return (uint32_t)__cvta_generic_to_shared(p);
}
#define CP_ASYNC16(dst, src) \
    asm volatile("cp.async.cg.shared.global [%0], [%1], 16;\n" :: "r"(dst), "l"(src))
#define CP_COMMIT() asm volatile("cp.async.commit_group;\n" ::: "memory")
#define CP_WAIT1()  asm volatile("cp.async.wait_group 1;\n" ::: "memory")

#define LDSM_X4(r, addr) \
    asm volatile("ldmatrix.sync.aligned.m8n8.x4.shared.b16 {%0,%1,%2,%3}, [%4];" \
        : "=r"((r)[0]), "=r"((r)[1]), "=r"((r)[2]), "=r"((r)[3]) : "r"(addr))

__device__ __forceinline__ void mma_bf16(float* d, const uint32_t* a, const uint32_t* b)
{
    asm volatile(
        "mma.sync.aligned.m16n8k16.row.col.f32.bf16.bf16.f32 "
        "{%0,%1,%2,%3}, {%4,%5,%6,%7}, {%8,%9}, {%0,%1,%2,%3};\n"
        : "+f"(d[0]), "+f"(d[1]), "+f"(d[2]), "+f"(d[3])
        : "r"(a[0]), "r"(a[1]), "r"(a[2]), "r"(a[3]), "r"(b[0]), "r"(b[1]));
}

// ---------------- fused conversion kernel (float4 vectorized) ----------------
// blocks [0, XB4): convert X (4 elems/thread); blocks [XB4, XB4+WB): W rows + norms
#define XB4 ((M_ROWS * K_DIM) / 1024)   // 3072
#define WB  (N_HID / 8)                 // 2048

__global__ void convert_all_kernel(const float* __restrict__ X,
                                   const float* __restrict__ W)
{
    if (blockIdx.x < XB4) {
        const int i = blockIdx.x * 256 + threadIdx.x;     // float4 index
        const float4 v = ((const float4*)X)[i];
        __nv_bfloat162 lo = __floats2bfloat162_rn(v.x, v.y);
        __nv_bfloat162 hi = __floats2bfloat162_rn(v.z, v.w);
        uint2 pk;
        pk.x = *(const uint32_t*)&lo;
        pk.y = *(const uint32_t*)&hi;
        *(uint2*)(X16 + 4 * (size_t)i) = pk;
        if (i < M_ROWS) g_ccnt[i] = 0;
    } else {
        const int row  = (blockIdx.x - XB4) * 8 + (threadIdx.x >> 5);
        const int lane = threadIdx.x & 31;
        const float4* w4 = (const float4*)(W + (size_t)row * K_DIM);
        float s = 0.0f;
#pragma unroll
        for (int k = 0; k < K_DIM / 128; k++) {           // 6 iters
            const float4 v = w4[lane + 32 * k];
            s = fmaf(v.x, v.x, s); s = fmaf(v.y, v.y, s);
            s = fmaf(v.z, v.z, s); s = fmaf(v.w, v.w, s);
            __nv_bfloat162 lo = __floats2bfloat162_rn(v.x, v.y);
            __nv_bfloat162 hi = __floats2bfloat162_rn(v.z, v.w);
            uint2 pk;
            pk.x = *(const uint32_t*)&lo;
            pk.y = *(const uint32_t*)&hi;
            *(uint2*)(W16 + (size_t)row * K_DIM + 4 * (lane + 32 * k)) = pk;
        }
#pragma unroll
        for (int o = 16; o; o >>= 1) s += __shfl_xor_sync(0xFFFFFFFFu, s, o);
        if (lane == 0) g_invnorm[row] = rsqrtf(s);
    }
}

// ---------------- encoder GEMM (bf16 mma.sync + ldmatrix, 3-stage) -------------
__device__ __forceinline__ void ldtile16(int m0, int n0, int kt,
                                         uint32_t* As, uint32_t* Bs, int t)
{
#pragma unroll
    for (int it = 0; it < 2; it++) {         // A: 128 rows x 4 granules
        const int g = t + it * 256;
        const int r = g >> 2;
        const int c = g & 3;
        CP_ASYNC16(cvta_shared(As + r * TS + c * 4),
                   X16 + (size_t)(m0 + r) * K_DIM + kt + c * 8);
    }
    {                                        // B: 64 rows x 4 granules
        const int r = t >> 2;
        const int c = t & 3;
        CP_ASYNC16(cvta_shared(Bs + r * TS + c * 4),
                   W16 + (size_t)(n0 + r) * K_DIM + kt + c * 8);
    }
}

__device__ __forceinline__ void cand_append(int row, int col, float v)
{
    if (v > THRESH) {
        const int q = atomicAdd(&g_ccnt[row], 1);
        if (q < CAP) {
            g_cidx[(size_t)row * CAP + q] = col;
            g_cval[(size_t)row * CAP + q] = v;
        }
    }
}

__global__ void __launch_bounds__(256, 3) encode_gemm(
    const float* __restrict__ bias, float* __restrict__ enc)
{
    extern __shared__ uint32_t smem[];   // NSTAGE * STAGE_TOT words

    const int t    = threadIdx.x;
    const int lane = t & 31;
    const int wid  = t >> 5;
    const int m0   = blockIdx.x * 128;
    const int n0   = blockIdx.y * 64;
    const int wm   = (wid & 3) * 32;     // warp m offset (4 warps in M)
    const int wn   = (wid >> 2) * 32;    // warp n offset (2 warps in N)
    const int fg   = lane >> 2;
    const int fc   = lane & 3;

    // per-thread ldmatrix address offsets (bytes) within a stage
    const uint32_t aoff = ((wm + (lane & 15)) * TS + ((lane >> 4) << 2)) * 4;
    const uint32_t boff = ((wn + (lane & 7) + ((lane >> 4) << 3)) * TS
                           + (((lane >> 3) & 1) << 2)) * 4;

    float acc[2][4][4];
#pragma unroll
    for (int i = 0; i < 2; i++)
#pragma unroll
        for (int j = 0; j < 4; j++)
#pragma unroll
            for (int r = 0; r < 4; r++) acc[i][j][r] = 0.0f;

    // prologue: stages 0 and 1 in flight
    ldtile16(m0, n0, 0,  smem,             smem + STG_A,             t);
    CP_COMMIT();
    ldtile16(m0, n0, 32, smem + STAGE_TOT, smem + STAGE_TOT + STG_A, t);
    CP_COMMIT();

    // zero this CTA's 128x64 output tile (overlapped; DRAM is idle in this kernel)
    {
        const float4 z = make_float4(0.f, 0.f, 0.f, 0.f);
#pragma unroll
        for (int k2 = 0; k2 < 8; k2++) {
            const int j = t + k2 * 256;          // 0..2047 float4 slots
            const int r = j >> 4;                // row 0..127
            const int c4 = j & 15;               // float4 col 0..15
            *(float4*)(enc + (size_t)(m0 + r) * N_HID + n0 + c4 * 4) = z;
        }
    }

    int stage = 0, nstage = 2;
    for (int kt = 0; kt < NKTILE; kt++) {
        CP_WAIT1();                // tile kt's loads complete (<=1 newer pending)
        __syncthreads();           // publish loads; all warps past reads of refill stage

        if (kt + 2 < NKTILE) {
            uint32_t* sb = smem + nstage * STAGE_TOT;
            ldtile16(m0, n0, (kt + 2) * 32, sb, sb + STG_A, t);
        }
        CP_COMMIT();               // keep group count consistent (may be empty)

        const uint32_t Ab = cvta_shared(smem + stage * STAGE_TOT);
        const uint32_t Bb = Ab + STG_A * 4;
#pragma unroll
        for (int ks = 0; ks < BKW; ks += 8) {
            uint32_t a[2][4], b[2][4];
#pragma unroll
            for (int mi = 0; mi < 2; mi++)
                LDSM_X4(a[mi], Ab + aoff + (mi * 16 * TS + ks) * 4);
#pragma unroll
            for (int njp = 0; njp < 2; njp++)
                LDSM_X4(b[njp], Bb + boff + (njp * 16 * TS + ks) * 4);
#pragma unroll
            for (int mi = 0; mi < 2; mi++)
#pragma unroll
                for (int nj = 0; nj < 4; nj++)
                    mma_bf16(acc[mi][nj], a[mi], &b[nj >> 1][(nj & 1) * 2]);
        }

        stage  = (stage  + 1 == NSTAGE) ? 0 : stage + 1;
        nstage = (nstage + 1 == NSTAGE) ? 0 : nstage + 1;
    }

    // epilogue: threshold + append candidates (no dense store)
#pragma unroll
    for (int nj = 0; nj < 4; nj++) {
        const int col = n0 + wn + nj * 8 + fc * 2;
        const float b0 = bias[col], b1 = bias[col + 1];
#pragma unroll
        for (int mi = 0; mi < 2; mi++) {
            const int row = m0 + wm + mi * 16 + fg;
            cand_append(row,     col,     acc[mi][nj][0] + b0);
            cand_append(row,     col + 1, acc[mi][nj][1] + b1);
            cand_append(row + 8, col,     acc[mi][nj][2] + b0);
            cand_append(row + 8, col + 1, acc[mi][nj][3] + b1);
        }
    }
}

// ---------------- fused top-k fixup + decode ----------------
__device__ __forceinline__ unsigned int f2u(float f)
{
    unsigned int b = __float_as_uint(f);
    return (b & 0x80000000u) ? ~b : (b | 0x80000000u);
}

// exact key of k-th largest over arr[0..n) (FALLBACK path only)
__device__ unsigned int radix_key(const float* arr, int n, int k,
                                  unsigned int* hist, unsigned int* cbuf,
                                  unsigned int* prefixSh, unsigned int* kSh, int t)
{
    if (t == 0) { *prefixSh = 0; *kSh = (unsigned int)k; }
    __syncthreads();
    for (int pass = 3; pass >= 0; --pass) {
        const int shift = pass * 8;
        hist[t] = 0;
        __syncthreads();
        const unsigned int prefix = *prefixSh;
        for (int i = t; i < n; i += 256) {
            const unsigned int u = f2u(arr[i]);
            bool cand = (pass == 3) || ((u >> (shift + 8)) == (prefix >> (shift + 8)));
            if (cand) atomicAdd(&hist[(u >> shift) & 0xFFu], 1u);
        }
        __syncthreads();
        cbuf[t] = hist[t];
        __syncthreads();
        for (int off = 1; off < 256; off <<= 1) {
            unsigned int v   = cbuf[t];
            unsigned int add = (t + off < 256) ? cbuf[t + off] : 0u;
            __syncthreads();
            cbuf[t] = v + add;
            __syncthreads();
        }
        const unsigned int kcur  = *kSh;
        const unsigned int here  = cbuf[t];
        const unsigned int above = (t < 255) ? cbuf[t + 1] : 0u;
        __syncthreads();
        if (here >= kcur && above < kcur) {
            *prefixSh = prefix | ((unsigned int)t << shift);
            *kSh = kcur - above;
        }
        __syncthreads();
    }
    return *prefixSh;
}

__global__ void __launch_bounds__(256) fixup_decode_kernel(
    const float* __restrict__ X, const float* __restrict__ W,
    const float* __restrict__ bias, float* __restrict__ enc,
    float* __restrict__ dec)
{
    const int row = blockIdx.x;
    float* p = enc + (size_t)row * N_HID;
    const int t = threadIdx.x;

    __shared__ __align__(16) float xrow[K_DIM];
    __shared__ float cval_s[CAP];          // staged candidate values
    __shared__ int   cidx_s[CAP];          // staged candidate indices
    __shared__ int   histo[1024];          // single-pass bucket histogram
    __shared__ int   tsum[256];            // per-thread bucket sums / scan
    __shared__ int   bstar;
    __shared__ unsigned int prefixSh, kSh; // fallback radix state
    __shared__ int nsel2, nacc;
    __shared__ int   sel_i[MAX_CAND];
    __shared__ float sel_v[MAX_CAND];
    __shared__ int   jsel[MAX_CAND];
    __shared__ float coef[MAX_CAND];

    if (t < K_DIM / 4)
        ((float4*)xrow)[t] = ((const float4*)(X + (size_t)row * K_DIM))[t];
    if (t == 0) { nsel2 = 0; nacc = 0; }
    histo[t] = 0; histo[t + 256] = 0; histo[t + 512] = 0; histo[t + 768] = 0;
    __syncthreads();

    const int cnt = g_ccnt[row];
    if (cnt >= RANK_SEL && cnt <= CAP) {
        // ---- single-pass histogram select; stage candidates in smem ----
        for (int i = t; i < cnt; i += 256) {
            const float v = g_cval[(size_t)row * CAP + i];
            cval_s[i] = v;
            cidx_s[i] = g_cidx[(size_t)row * CAP + i];
            int b = (int)((f2u(v) >> 16) - 0xC000u);
            b = (b > 1023) ? 1023 : b;
            atomicAdd(&histo[b], 1);
        }
        __syncthreads();
        tsum[t] = histo[4 * t] + histo[4 * t + 1] + histo[4 * t + 2] + histo[4 * t + 3];
        __syncthreads();
        for (int off = 1; off < 256; off <<= 1) {       // suffix scan of tsum
            int v = tsum[t];
            int add = (t + off < 256) ? tsum[t + off] : 0;
            __syncthreads();
            tsum[t] = v + add;
            __syncthreads();
        }
        {
            const int above = (t < 255) ? tsum[t + 1] : 0;
            int suf = above;
#pragma unroll
            for (int k2 = 3; k2 >= 0; k2--) {           // suffix within this thread's 4 bins
                const int b = 4 * t + k2;
                suf += histo[b];
                if (suf >= RANK_SEL && (suf - histo[b]) < RANK_SEL) bstar = b;
            }
        }
        __syncthreads();
        const int bth = bstar;
        for (int i = t; i < cnt; i += 256) {
            int b = (int)((f2u(cval_s[i]) >> 16) - 0xC000u);
            b = (b > 1023) ? 1023 : b;
            if (b >= bth) {
                const int q = atomicAdd(&nsel2, 1);
                if (q < MAX_CAND) sel_i[q] = cidx_s[i];
            }
        }
    } else {
        // fallback (statistically never taken): exact full-row recompute
        for (int n = t; n < N_HID; n += 256) {
            const float* wr = W + (size_t)n * K_DIM;
            float s = 0.0f;
            for (int k2 = 0; k2 < K_DIM; k2++) s = fmaf(xrow[k2], wr[k2], s);
            p[n] = s + bias[n];
        }
        __syncthreads();
        const unsigned int key = radix_key(p, N_HID, RANK_SEL,
                                           (unsigned int*)histo, (unsigned int*)tsum,
                                           &prefixSh, &kSh, t);
        for (int i = t; i < N_HID; i += 256) {
            if (f2u(p[i]) >= key) {
                const int q = atomicAdd(&nsel2, 1);
                if (q < MAX_CAND) sel_i[q] = i;
            }
        }
        __syncthreads();
        float4 z4 = make_float4(0.f, 0.f, 0.f, 0.f);
        for (int i = t; i < N_HID / 4; i += 256) ((float4*)p)[i] = z4;  // re-zero
    }
    __syncthreads();
    const int nc = (nsel2 < MAX_CAND) ? nsel2 : MAX_CAND;

    // exact fp32 dot products for selected candidates (one warp per candidate,
    // float4 loads: 6 LDG.128 + 6 LDS.128 per lane)
    const int lane = t & 31, w = t >> 5;
    const float4* xr4 = (const float4*)xrow;
    for (int i = w; i < nc; i += 8) {
        const float4* wr4 = (const float4*)(W + (size_t)sel_i[i] * K_DIM);
        float s = 0.0f;
#pragma unroll
        for (int k2 = 0; k2 < K_DIM / 128; k2++) {       // 6 iters
            const float4 wv = wr4[lane + 32 * k2];
            const float4 xv = xr4[lane + 32 * k2];
            s = fmaf(xv.x, wv.x, s);
            s = fmaf(xv.y, wv.y, s);
            s = fmaf(xv.z, wv.z, s);
            s = fmaf(xv.w, wv.w, s);
        }
#pragma unroll
        for (int o = 16; o; o >>= 1) s += __shfl_xor_sync(0xFFFFFFFFu, s, o);
        if (lane == 0) sel_v[i] = s + bias[sel_i[i]];
    }
    __syncthreads();

    // exact rank; keep if fewer than K_SPARSE strictly greater (keeps ties);
    // scatter exact value to enc and gather (idx, coef) for the fused decode
    if (t < nc) {
        const float v = sel_v[t];
        int cg = 0;
        for (int j = 0; j < nc; j++) cg += (sel_v[j] > v);
        if (cg < K_SPARSE) {
            const int idx = sel_i[t];
            p[idx] = v;
            const int q = atomicAdd(&nacc, 1);
            jsel[q] = idx;
            coef[q] = v * g_invnorm[idx];
        }
    }
    __syncthreads();

    // fused decode: dec[row,:] = sum_j coef_j * W[jsel_j,:]  (W rows are L1-hot)
    const int ns = nacc;
    float a0 = 0.0f, a1 = 0.0f, a2 = 0.0f;
    for (int j = 0; j < ns; ++j) {
        const float* wr = W + (size_t)jsel[j] * K_DIM;
        const float cf = coef[j];
        a0 = fmaf(cf, wr[t],       a0);
        a1 = fmaf(cf, wr[t + 256], a1);
        a2 = fmaf(cf, wr[t + 512], a2);
    }
    float* o = dec + (size_t)row * K_DIM;
    o[t] = a0; o[t + 256] = a1; o[t + 512] = a2;
}

// ---------------- launch ----------------
extern "C" void kernel_launch(void* const* d_in, const int* in_sizes, int n_in,
                              void* d_out, int out_size)
{
    const float* x = (const float*)d_in[0];
    const float* W = (const float*)d_in[1];
    const float* b = (const float*)d_in[2];
    float* out = (float*)d_out;

    float* dec = out;                               // [4096, 768]
    float* enc = out + (size_t)M_ROWS * K_DIM;      // [4096, 16384]

    convert_all_kernel<<<XB4 + WB, 256>>>(x, W);

    const int dyn_smem = NSTAGE * STAGE_TOT * 4;    // 46080 bytes
    cudaFuncSetAttribute(encode_gemm, cudaFuncAttributeMaxDynamicSharedMemorySize, dyn_smem);

    dim3 ggrid(M_ROWS / 128, N_HID / 64);           // x fast: consecutive CTAs share B tile
    encode_gemm<<<ggrid, 256, dyn_smem>>>(b, enc);
    fixup_decode_kernel<<<M_ROWS, 256>>>(x, W, b, enc, dec);
}